// round 16
// baseline (speedup 1.0000x reference)
#include <cuda_runtime.h>
#include <cuda_bf16.h>
#include <cuda_fp16.h>
#include <cstdint>

// ============================================================================
// BagSelfAttention: B=8, N=2048, L=1280, H=160
// Round 16: R11 schedule + fp16 path (vproj/attnv) rebuilt as 128-thread CTAs
//           with 64x64 warp tiles (255-reg budget at 2 CTAs/SM) to halve
//           smem fragment traffic per MAC. 3-term bf16 path unchanged.
// ============================================================================

#define BB   8
#define NN   2048
#define LL   1280
#define HH   160
#define MTOT (BB * NN)
#define KQK  160
#define NWQK 384

__device__ __align__(1024) __nv_bfloat16 g_xh [MTOT * LL];
__device__ __align__(1024) __nv_bfloat16 g_xl [MTOT * LL];
__device__ __align__(1024) __half        g_xf [MTOT * LL];
__device__ __align__(1024) __nv_bfloat16 g_wqkh[NWQK * LL];
__device__ __align__(1024) __nv_bfloat16 g_wqkl[NWQK * LL];
__device__ __align__(1024) __half        g_wvh [LL * LL];
__device__ __align__(1024) __nv_bfloat16 g_qh  [MTOT * KQK];
__device__ __align__(1024) __nv_bfloat16 g_ql  [MTOT * KQK];
__device__ __align__(1024) __nv_bfloat16 g_kh  [MTOT * KQK];
__device__ __align__(1024) __nv_bfloat16 g_kl  [MTOT * KQK];
__device__ __align__(1024) float         g_e   [MTOT * NN];
__device__ __align__(1024) __half        g_ath [MTOT * NN];
__device__ __align__(1024) __half        g_vth [BB * LL * NN];
__device__ __align__(1024) float         g_bqk [NWQK];

__device__ __forceinline__ uint32_t smem_u32(const void* p) {
    uint32_t a;
    asm("{ .reg .u64 t; cvta.to.shared.u64 t, %1; cvt.u32.u64 %0, t; }"
        : "=r"(a) : "l"(p));
    return a;
}

#define CPA(dst, src) \
    asm volatile("cp.async.cg.shared.global [%0], [%1], 16;" :: "r"(dst), "l"(src) : "memory")
#define CPCOMMIT() asm volatile("cp.async.commit_group;" ::: "memory")
#define CPWAIT1()  asm volatile("cp.async.wait_group 1;" ::: "memory")

#define LDSM4(R, A) \
    asm volatile("ldmatrix.sync.aligned.m8n8.x4.shared.b16 {%0,%1,%2,%3}, [%4];" \
                 : "=r"((R)[0]), "=r"((R)[1]), "=r"((R)[2]), "=r"((R)[3]) : "r"(A))

#define MMA_BF16(C, A, B0, B1) \
    asm volatile("mma.sync.aligned.m16n8k16.row.col.f32.bf16.bf16.f32 " \
                 "{%0,%1,%2,%3}, {%4,%5,%6,%7}, {%8,%9}, {%0,%1,%2,%3};" \
                 : "+f"((C)[0]), "+f"((C)[1]), "+f"((C)[2]), "+f"((C)[3]) \
                 : "r"((A)[0]), "r"((A)[1]), "r"((A)[2]), "r"((A)[3]), "r"(B0), "r"(B1))

#define MMA_F16(C, A, B0, B1) \
    asm volatile("mma.sync.aligned.m16n8k16.row.col.f32.f16.f16.f32 " \
                 "{%0,%1,%2,%3}, {%4,%5,%6,%7}, {%8,%9}, {%0,%1,%2,%3};" \
                 : "+f"((C)[0]), "+f"((C)[1]), "+f"((C)[2]), "+f"((C)[3]) \
                 : "r"((A)[0]), "r"((A)[1]), "r"((A)[2]), "r"((A)[3]), "r"(B0), "r"(B1))

__device__ __forceinline__ void split_store(float v, __nv_bfloat16* h, __nv_bfloat16* l,
                                            long long idx) {
    __nv_bfloat16 hi = __float2bfloat16(v);
    h[idx] = hi;
    l[idx] = __float2bfloat16(v - __bfloat162float(hi));
}

// ---------------- conversion kernels ----------------
__global__ void split3_kernel(const float* __restrict__ x,
                              __nv_bfloat16* __restrict__ h,
                              __nv_bfloat16* __restrict__ l,
                              __half* __restrict__ f, long long n) {
    long long i = ((long long)blockIdx.x * blockDim.x + threadIdx.x) * 4;
    if (i >= n) return;
    float4 v = *(const float4*)(x + i);
    __nv_bfloat162 h0, h1, l0, l1;
    h0.x = __float2bfloat16(v.x); l0.x = __float2bfloat16(v.x - __bfloat162float(h0.x));
    h0.y = __float2bfloat16(v.y); l0.y = __float2bfloat16(v.y - __bfloat162float(h0.y));
    h1.x = __float2bfloat16(v.z); l1.x = __float2bfloat16(v.z - __bfloat162float(h1.x));
    h1.y = __float2bfloat16(v.w); l1.y = __float2bfloat16(v.w - __bfloat162float(h1.y));
    *(__nv_bfloat162*)(h + i) = h0; *(__nv_bfloat162*)(h + i + 2) = h1;
    *(__nv_bfloat162*)(l + i) = l0; *(__nv_bfloat162*)(l + i + 2) = l1;
    __half2 f0, f1;
    f0.x = __float2half(v.x); f0.y = __float2half(v.y);
    f1.x = __float2half(v.z); f1.y = __float2half(v.w);
    *(__half2*)(f + i) = f0; *(__half2*)(f + i + 2) = f1;
}

__global__ void tohalf_kernel(const float* __restrict__ x,
                              __half* __restrict__ h, long long n) {
    long long i = ((long long)blockIdx.x * blockDim.x + threadIdx.x) * 4;
    if (i >= n) return;
    float4 v = *(const float4*)(x + i);
    __half2 h0, h1;
    h0.x = __float2half(v.x); h0.y = __float2half(v.y);
    h1.x = __float2half(v.z); h1.y = __float2half(v.w);
    *(__half2*)(h + i) = h0; *(__half2*)(h + i + 2) = h1;
}

__global__ void build_wqk_kernel(const float* __restrict__ Wq, const float* __restrict__ bq,
                                 const float* __restrict__ Wk, const float* __restrict__ bk,
                                 __nv_bfloat16* __restrict__ wh, __nv_bfloat16* __restrict__ wl,
                                 float* __restrict__ bqk) {
    long long i = (long long)blockIdx.x * blockDim.x + threadIdx.x;
    if (i >= (long long)NWQK * LL) return;
    int r = (int)(i / LL), c = (int)(i % LL);
    float v = (r < HH) ? Wq[r * LL + c] : (r < 2 * HH) ? Wk[(r - HH) * LL + c] : 0.f;
    split_store(v, wh, wl, i);
    if (c == 0) bqk[r] = (r < HH) ? bq[r] : (r < 2 * HH) ? bk[r - HH] : 0.f;
}

// ---------------- softmax (fp32 in, fp16 out) ----------------
__global__ __launch_bounds__(256)
void softmax_f16_kernel(const float* __restrict__ E, __half* __restrict__ ah) {
    const long long row = blockIdx.x;
    const float* p = E + row * NN;
    const int tid = threadIdx.x;

    float4 v0 = *(const float4*)(p + tid * 4);
    float4 v1 = *(const float4*)(p + 1024 + tid * 4);

    float m = fmaxf(fmaxf(fmaxf(v0.x, v0.y), fmaxf(v0.z, v0.w)),
                    fmaxf(fmaxf(v1.x, v1.y), fmaxf(v1.z, v1.w)));
    #pragma unroll
    for (int o = 16; o > 0; o >>= 1) m = fmaxf(m, __shfl_xor_sync(0xffffffffu, m, o));

    __shared__ float rmax[8], rsum[8];
    if ((tid & 31) == 0) rmax[tid >> 5] = m;
    __syncthreads();
    float rowmax = rmax[0];
    #pragma unroll
    for (int i = 1; i < 8; i++) rowmax = fmaxf(rowmax, rmax[i]);

    v0.x = __expf(v0.x - rowmax); v0.y = __expf(v0.y - rowmax);
    v0.z = __expf(v0.z - rowmax); v0.w = __expf(v0.w - rowmax);
    v1.x = __expf(v1.x - rowmax); v1.y = __expf(v1.y - rowmax);
    v1.z = __expf(v1.z - rowmax); v1.w = __expf(v1.w - rowmax);

    float s = v0.x + v0.y + v0.z + v0.w + v1.x + v1.y + v1.z + v1.w;
    #pragma unroll
    for (int o = 16; o > 0; o >>= 1) s += __shfl_xor_sync(0xffffffffu, s, o);
    if ((tid & 31) == 0) rsum[tid >> 5] = s;
    __syncthreads();
    float tot = 0.f;
    #pragma unroll
    for (int i = 0; i < 8; i++) tot += rsum[i];

    const float inv = 1.f / tot;
    long long base = row * NN;
    __half2 o0, o1;
    o0.x = __float2half(v0.x * inv); o0.y = __float2half(v0.y * inv);
    o1.x = __float2half(v0.z * inv); o1.y = __float2half(v0.w * inv);
    *(__half2*)(ah + base + tid * 4) = o0;
    *(__half2*)(ah + base + tid * 4 + 2) = o1;
    o0.x = __float2half(v1.x * inv); o0.y = __float2half(v1.y * inv);
    o1.x = __float2half(v1.z * inv); o1.y = __float2half(v1.w * inv);
    *(__half2*)(ah + base + 1024 + tid * 4) = o0;
    *(__half2*)(ah + base + 1024 + tid * 4 + 2) = o1;
}

// ---------------- 3-term bf16 split GEMM body (128x128, BKT=32, 256 thr) ----
template <int MODE>
__device__ __forceinline__
void gemm_body3(char* smem, int m0, int n0, int bz, int nvalid,
                const uint16_t* __restrict__ Ah, const uint16_t* __restrict__ Al,
                int lda, long long sA,
                const uint16_t* __restrict__ Bh, const uint16_t* __restrict__ Bl,
                int ldb, long long sB,
                float* __restrict__ fout, const float* __restrict__ bias,
                __nv_bfloat16* __restrict__ o0, __nv_bfloat16* __restrict__ o1,
                __nv_bfloat16* __restrict__ o2, __nv_bfloat16* __restrict__ o3,
                int K)
{
    constexpr int TSZ = 128 * 64;
    constexpr int SSZ = 4 * TSZ;
    const uint32_t sb0 = smem_u32(smem);

    const int tid = threadIdx.x, lane = tid & 31, wid = tid >> 5;

    Ah += bz * sA; Bh += bz * sB; Al += bz * sA; Bl += bz * sB;

    auto swz = [](int row, int ch) -> uint32_t {
        return (uint32_t)(row * 64 + ((ch ^ ((row >> 1) & 3)) << 4));
    };

    auto load_stage = [&](int kt, int s) {
        const uint32_t sb = sb0 + (uint32_t)s * SSZ;
        const int k0 = kt * 32;
        #pragma unroll
        for (int i = 0; i < 2; i++) {
            int c = tid + i * 256;
            int row = c >> 2, ch = c & 3;
            uint32_t off = swz(row, ch);
            CPA(sb + off,            Ah + (long long)(m0 + row) * lda + k0 + ch * 8);
            CPA(sb + TSZ + off,      Al + (long long)(m0 + row) * lda + k0 + ch * 8);
            CPA(sb + 2 * TSZ + off,  Bh + (long long)(n0 + row) * ldb + k0 + ch * 8);
            CPA(sb + 3 * TSZ + off,  Bl + (long long)(n0 + row) * ldb + k0 + ch * 8);
        }
        CPCOMMIT();
    };

    const int nk = K / 32;
    load_stage(0, 0);
    load_stage(1, 1);

    const int wm = (wid >> 2) * 64;
    const int wn = (wid & 3) * 32;
    const bool active = (wn < nvalid);

    float acc[4][4][4];
    #pragma unroll
    for (int i = 0; i < 4; i++)
        #pragma unroll
        for (int j = 0; j < 4; j++)
            #pragma unroll
            for (int r = 0; r < 4; r++) acc[i][j][r] = 0.f;

    const int arow = wm + (lane & 7) + (lane & 8);
    const int brow = wn + (lane & 7) + ((lane & 16) >> 1);
    const int acc_k = (lane >> 4);
    const int bcc_k = ((lane >> 3) & 1);

    for (int t = 0; t < nk; t++) {
        const int s = t % 3;
        CPWAIT1();
        __syncthreads();
        if (t + 2 < nk) load_stage(t + 2, (t + 2) % 3);
        else CPCOMMIT();

        if (active) {
            const uint32_t sb = sb0 + (uint32_t)s * SSZ;
            #pragma unroll
            for (int ks = 0; ks < 2; ks++) {
                uint32_t ah[4][4];
                #pragma unroll
                for (int i = 0; i < 4; i++) {
                    int row = arow + i * 16;
                    int cc  = ks * 2 + acc_k;
                    LDSM4(ah[i], sb + swz(row, cc));
                }
                uint32_t bh[4][2];
                #pragma unroll
                for (int j2 = 0; j2 < 2; j2++) {
                    int row = brow + j2 * 16;
                    int cc  = ks * 2 + bcc_k;
                    uint32_t r[4];
                    LDSM4(r, sb + 2 * TSZ + swz(row, cc));
                    bh[2 * j2][0] = r[0]; bh[2 * j2][1] = r[1];
                    bh[2 * j2 + 1][0] = r[2]; bh[2 * j2 + 1][1] = r[3];
                }
                #pragma unroll
                for (int i = 0; i < 4; i++)
                    #pragma unroll
                    for (int j = 0; j < 4; j++)
                        MMA_BF16(acc[i][j], ah[i], bh[j][0], bh[j][1]);

                {
                    uint32_t bl[4][2];
                    #pragma unroll
                    for (int j2 = 0; j2 < 2; j2++) {
                        int row = brow + j2 * 16;
                        int cc  = ks * 2 + bcc_k;
                        uint32_t r[4];
                        LDSM4(r, sb + 3 * TSZ + swz(row, cc));
                        bl[2 * j2][0] = r[0]; bl[2 * j2][1] = r[1];
                        bl[2 * j2 + 1][0] = r[2]; bl[2 * j2 + 1][1] = r[3];
                    }
                    #pragma unroll
                    for (int i = 0; i < 4; i++)
                        #pragma unroll
                        for (int j = 0; j < 4; j++)
                            MMA_BF16(acc[i][j], ah[i], bl[j][0], bl[j][1]);
                }
                #pragma unroll
                for (int i = 0; i < 4; i++) {
                    int row = arow + i * 16;
                    int cc  = ks * 2 + acc_k;
                    LDSM4(ah[i], sb + TSZ + swz(row, cc));
                }
                #pragma unroll
                for (int i = 0; i < 4; i++)
                    #pragma unroll
                    for (int j = 0; j < 4; j++)
                        MMA_BF16(acc[i][j], ah[i], bh[j][0], bh[j][1]);
            }
        }
    }

    if (!active) return;
    const int g = lane >> 2, t4 = lane & 3;
    #pragma unroll
    for (int i = 0; i < 4; i++) {
        #pragma unroll
        for (int j = 0; j < 4; j++) {
            #pragma unroll
            for (int half = 0; half < 2; half++) {
                const int m = m0 + wm + i * 16 + g + half * 8;
                const int n = n0 + wn + j * 8 + t4 * 2;
                float v0 = acc[i][j][half * 2 + 0];
                float v1 = acc[i][j][half * 2 + 1];
                if (MODE == 2) {
                    float2* dst = (float2*)(fout + (long long)bz * NN * NN +
                                            (long long)m * NN + n);
                    *dst = make_float2(v0, v1);
                } else {
                    #pragma unroll
                    for (int e = 0; e < 2; e++) {
                        int nn = n + e;
                        float val = (e ? v1 : v0) + bias[nn];
                        if (nn < HH)
                            split_store(val, o0, o1, (long long)m * KQK + nn);
                        else if (nn < 2 * HH)
                            split_store(val, o2, o3, (long long)m * KQK + (nn - HH));
                    }
                }
            }
        }
    }
}

// ---------------- fp16 GEMM body: 128 threads, 64x64 warp tiles -------------
// CTA tile 128x128, 4 warps (2x2), BKT=64. 255-reg budget at 2 CTAs/SM.
// MODE 1: v-proj (bias, transposed fp16 write)  MODE 3: attn@v (residual, fp32)
template <int MODE>
__device__ __forceinline__
void gemm_f16w(char* smem, int m0, int n0, int bz,
               const uint16_t* __restrict__ A, int lda, long long sA,
               const uint16_t* __restrict__ B, int ldb, long long sB,
               float* __restrict__ fout, const float* __restrict__ bias,
               const float* __restrict__ resid, __half* __restrict__ ohalf,
               int K)
{
    constexpr int TSZ = 128 * 128;  // 16 KB per operand tile (BKT=64)
    constexpr int SSZ = 2 * TSZ;    // 32 KB per stage
    const uint32_t sb0 = smem_u32(smem);

    const int tid = threadIdx.x, lane = tid & 31, wid = tid >> 5;

    A += bz * sA; B += bz * sB;

    auto swz = [](int row, int ch) -> uint32_t {
        return (uint32_t)(row * 128 + ((ch ^ (row & 7)) << 4));
    };

    auto load_stage = [&](int kt, int s) {
        const uint32_t sb = sb0 + (uint32_t)s * SSZ;
        const int k0 = kt * 64;
        #pragma unroll
        for (int i = 0; i < 8; i++) {
            int c = tid + i * 128;          // 1024 chunks per tile
            int row = c >> 3, ch = c & 7;
            uint32_t off = swz(row, ch);
            CPA(sb + off,       A + (long long)(m0 + row) * lda + k0 + ch * 8);
            CPA(sb + TSZ + off, B + (long long)(n0 + row) * ldb + k0 + ch * 8);
        }
        CPCOMMIT();
    };

    const int nk = K / 64;
    load_stage(0, 0);
    load_stage(1, 1);

    const int wm = (wid >> 1) * 64;  // 2 warps in M
    const int wn = (wid & 1) * 64;   // 2 warps in N

    float acc[4][8][4];
    #pragma unroll
    for (int i = 0; i < 4; i++)
        #pragma unroll
        for (int j = 0; j < 8; j++)
            #pragma unroll
            for (int r = 0; r < 4; r++) acc[i][j][r] = 0.f;

    const int arow = wm + (lane & 7) + (lane & 8);
    const int brow = wn + (lane & 7) + ((lane & 16) >> 1);
    const int acc_k = (lane >> 4);
    const int bcc_k = ((lane >> 3) & 1);

    for (int t = 0; t < nk; t++) {
        const int s = t % 3;
        CPWAIT1();
        __syncthreads();
        if (t + 2 < nk) load_stage(t + 2, (t + 2) % 3);
        else CPCOMMIT();

        const uint32_t sb = sb0 + (uint32_t)s * SSZ;
        #pragma unroll
        for (int ks = 0; ks < 4; ks++) {
            uint32_t af[4][4];
            #pragma unroll
            for (int i = 0; i < 4; i++) {
                int row = arow + i * 16;
                int cc  = ks * 2 + acc_k;
                LDSM4(af[i], sb + swz(row, cc));
            }
            uint32_t bf[8][2];
            #pragma unroll
            for (int j2 = 0; j2 < 4; j2++) {
                int row = brow + j2 * 16;
                int cc  = ks * 2 + bcc_k;
                uint32_t r[4];
                LDSM4(r, sb + TSZ + swz(row, cc));
                bf[2 * j2][0] = r[0]; bf[2 * j2][1] = r[1];
                bf[2 * j2 + 1][0] = r[2]; bf[2 * j2 + 1][1] = r[3];
            }
            #pragma unroll
            for (int i = 0; i < 4; i++)
                #pragma unroll
                for (int j = 0; j < 8; j++)
                    MMA_F16(acc[i][j], af[i], bf[j][0], bf[j][1]);
        }
    }

    const int g = lane >> 2, t4 = lane & 3;
    #pragma unroll
    for (int i = 0; i < 4; i++) {
        #pragma unroll
        for (int j = 0; j < 8; j++) {
            #pragma unroll
            for (int half = 0; half < 2; half++) {
                const int m = m0 + wm + i * 16 + g + half * 8;
                const int n = n0 + wn + j * 8 + t4 * 2;
                float v0 = acc[i][j][half * 2 + 0];
                float v1 = acc[i][j][half * 2 + 1];
                if (MODE == 3) {
                    const long long off = (long long)bz * NN * LL + (long long)m * LL + n;
                    float2 rx = *(const float2*)(resid + off);
                    *(float2*)(fout + off) = make_float2(v0 + rx.x, v1 + rx.y);
                } else {  // MODE 1: transposed fp16 write into vT
                    const int b = m >> 11, ii = m & (NN - 1);
                    long long i0 = (((long long)(b * LL + n)) << 11) + ii;
                    long long i1 = (((long long)(b * LL + n + 1)) << 11) + ii;
                    ohalf[i0] = __float2half(v0 + bias[n]);
                    ohalf[i1] = __float2half(v1 + bias[n + 1]);
                }
            }
        }
    }
}

// ---------------- kernel wrappers ----------------
__global__ __launch_bounds__(256, 2)
void proj_qk_kernel(const __nv_bfloat16* __restrict__ xh, const __nv_bfloat16* __restrict__ xl,
                    const __nv_bfloat16* __restrict__ wqkh, const __nv_bfloat16* __restrict__ wqkl,
                    const float* __restrict__ bqk,
                    __nv_bfloat16* __restrict__ qh, __nv_bfloat16* __restrict__ ql,
                    __nv_bfloat16* __restrict__ kh, __nv_bfloat16* __restrict__ kl)
{
    extern __shared__ char smem[];
    const int bx = blockIdx.x;
    const int nvalid = (bx == 2) ? 64 : 128;
    gemm_body3<0>(smem, blockIdx.y * 128, bx * 128, 0, nvalid,
                  (const uint16_t*)xh, (const uint16_t*)xl, LL, 0,
                  (const uint16_t*)wqkh, (const uint16_t*)wqkl, LL, 0,
                  nullptr, bqk, qh, ql, kh, kl, LL);
}

__global__ __launch_bounds__(128, 2)
void proj_v_kernel(const __half* __restrict__ xf, const __half* __restrict__ wvh,
                   const float* __restrict__ bv, __half* __restrict__ vth)
{
    extern __shared__ char smem[];
    gemm_f16w<1>(smem, blockIdx.y * 128, blockIdx.x * 128, 0,
                 (const uint16_t*)xf, LL, 0, (const uint16_t*)wvh, LL, 0,
                 nullptr, bv, nullptr, vth, LL);
}

__global__ __launch_bounds__(256, 2)
void energy_kernel(const __nv_bfloat16* __restrict__ qh, const __nv_bfloat16* __restrict__ ql,
                   const __nv_bfloat16* __restrict__ kh, const __nv_bfloat16* __restrict__ kl,
                   float* __restrict__ e)
{
    extern __shared__ char smem[];
    gemm_body3<2>(smem, blockIdx.y * 128, blockIdx.x * 128, blockIdx.z, 128,
                  (const uint16_t*)qh, (const uint16_t*)ql, KQK, (long long)NN * KQK,
                  (const uint16_t*)kh, (const uint16_t*)kl, KQK, (long long)NN * KQK,
                  e, nullptr, nullptr, nullptr, nullptr, nullptr, KQK);
}

__global__ __launch_bounds__(128, 2)
void attnv_kernel(const __half* __restrict__ ath, const __half* __restrict__ vth,
                  const float* __restrict__ x, float* __restrict__ out)
{
    extern __shared__ char smem[];
    gemm_f16w<3>(smem, blockIdx.y * 128, blockIdx.x * 128, blockIdx.z,
                 (const uint16_t*)ath, NN, (long long)NN * NN,
                 (const uint16_t*)vth, NN, (long long)LL * NN,
                 out, nullptr, x, nullptr, NN);
}

// ---------------- host side ----------------
extern "C" void kernel_launch(void* const* d_in, const int* in_sizes, int n_in,
                              void* d_out, int out_size) {
    const float* x  = (const float*)d_in[0];
    const float* Wq = (const float*)d_in[1];
    const float* bq = (const float*)d_in[2];
    const float* Wk = (const float*)d_in[3];
    const float* bk = (const float*)d_in[4];
    const float* Wv = (const float*)d_in[5];
    const float* bv = (const float*)d_in[6];
    float* out = (float*)d_out;

    __nv_bfloat16 *xh, *xl, *wqkh, *wqkl, *qh, *ql, *kh, *kl;
    __half *xf, *wvh, *ath, *vth;
    float *e, *bqk;
    cudaGetSymbolAddress((void**)&xh, g_xh);     cudaGetSymbolAddress((void**)&xl, g_xl);
    cudaGetSymbolAddress((void**)&xf, g_xf);
    cudaGetSymbolAddress((void**)&wqkh, g_wqkh); cudaGetSymbolAddress((void**)&wqkl, g_wqkl);
    cudaGetSymbolAddress((void**)&wvh, g_wvh);
    cudaGetSymbolAddress((void**)&qh, g_qh);     cudaGetSymbolAddress((void**)&ql, g_ql);
    cudaGetSymbolAddress((void**)&kh, g_kh);     cudaGetSymbolAddress((void**)&kl, g_kl);
    cudaGetSymbolAddress((void**)&e, g_e);
    cudaGetSymbolAddress((void**)&ath, g_ath);
    cudaGetSymbolAddress((void**)&vth, g_vth);
    cudaGetSymbolAddress((void**)&bqk, g_bqk);

    constexpr int SMEM = 3 * 32768;
    static cudaStream_t s1 = nullptr;
    static cudaEvent_t evPre = nullptr, evV = nullptr;
    if (!s1) {
        cudaFuncSetAttribute((const void*)proj_qk_kernel,
                             cudaFuncAttributeMaxDynamicSharedMemorySize, SMEM);
        cudaFuncSetAttribute((const void*)proj_v_kernel,
                             cudaFuncAttributeMaxDynamicSharedMemorySize, SMEM);
        cudaFuncSetAttribute((const void*)energy_kernel,
                             cudaFuncAttributeMaxDynamicSharedMemorySize, SMEM);
        cudaFuncSetAttribute((const void*)attnv_kernel,
                             cudaFuncAttributeMaxDynamicSharedMemorySize, SMEM);
        cudaStreamCreateWithFlags(&s1, cudaStreamNonBlocking);
        cudaEventCreateWithFlags(&evPre, cudaEventDisableTiming);
        cudaEventCreateWithFlags(&evV, cudaEventDisableTiming);
    }

    // conversions (stream 0) — fused single-pass over x
    {
        long long n = (long long)MTOT * LL;
        split3_kernel<<<(unsigned)(n / 4 / 256), 256>>>(x, xh, xl, xf, n);
    }
    build_wqk_kernel<<<(NWQK * LL + 255) / 256, 256>>>(Wq, bq, Wk, bk, wqkh, wqkl, bqk);
    {
        long long n = (long long)LL * LL;
        tohalf_kernel<<<(unsigned)((n / 4 + 255) / 256), 256>>>(Wv, wvh, n);
    }

    // fork: v-proj on s1, overlapping qkproj tail + energy + softmax
    cudaEventRecord(evPre, 0);
    cudaStreamWaitEvent(s1, evPre, 0);
    proj_v_kernel<<<dim3(LL / 128, MTOT / 128, 1), 128, SMEM, s1>>>(xf, wvh, bv, vth);
    cudaEventRecord(evV, s1);

    // stream 0: qk projection -> energy -> softmax
    proj_qk_kernel<<<dim3(3, MTOT / 128, 1), 256, SMEM>>>(
        xh, xl, wqkh, wqkl, bqk, qh, ql, kh, kl);
    energy_kernel<<<dim3(NN / 128, NN / 128, BB), 256, SMEM>>>(qh, ql, kh, kl, e);
    softmax_f16_kernel<<<MTOT, 256>>>(e, ath);

    // join v-proj, then attn@v + residual
    cudaStreamWaitEvent(0, evV, 0);
    attnv_kernel<<<dim3(LL / 128, NN / 128, BB), 128, SMEM>>>(ath, vth, x, out);
}

// round 17
// speedup vs baseline: 1.0033x; 1.0033x over previous
#include <cuda_runtime.h>
#include <cuda_bf16.h>
#include <cuda_fp16.h>
#include <cstdint>

// ============================================================================
// BagSelfAttention: B=8, N=2048, L=1280, H=160
// FINAL (R11 configuration — fastest of 12 passing variants, 631.3us):
//   - x -> bf16 hi/lo + fp16 in one fused pass
//   - qk path: 3-term bf16 hi/lo split HMMA (128x128, BKT=32, 2 CTAs/SM),
//     pad-tile warp skip on the stacked Wq|Wk tile
//   - v path: single-term fp16 HMMA (128x128, BKT=64, 2 CTAs/SM),
//     forked onto a second stream overlapping qkproj/energy/softmax
//   - energy: exact K=160; fp32 E; fp32 softmax -> fp16 A
//   - attn@v: fp16 HMMA + fp32 residual epilogue
// ============================================================================

#define BB   8
#define NN   2048
#define LL   1280
#define HH   160
#define MTOT (BB * NN)
#define KQK  160
#define NWQK 384

__device__ __align__(1024) __nv_bfloat16 g_xh [MTOT * LL];
__device__ __align__(1024) __nv_bfloat16 g_xl [MTOT * LL];
__device__ __align__(1024) __half        g_xf [MTOT * LL];
__device__ __align__(1024) __nv_bfloat16 g_wqkh[NWQK * LL];
__device__ __align__(1024) __nv_bfloat16 g_wqkl[NWQK * LL];
__device__ __align__(1024) __half        g_wvh [LL * LL];
__device__ __align__(1024) __nv_bfloat16 g_qh  [MTOT * KQK];
__device__ __align__(1024) __nv_bfloat16 g_ql  [MTOT * KQK];
__device__ __align__(1024) __nv_bfloat16 g_kh  [MTOT * KQK];
__device__ __align__(1024) __nv_bfloat16 g_kl  [MTOT * KQK];
__device__ __align__(1024) float         g_e   [MTOT * NN];
__device__ __align__(1024) __half        g_ath [MTOT * NN];
__device__ __align__(1024) __half        g_vth [BB * LL * NN];
__device__ __align__(1024) float         g_bqk [NWQK];

__device__ __forceinline__ uint32_t smem_u32(const void* p) {
    uint32_t a;
    asm("{ .reg .u64 t; cvta.to.shared.u64 t, %1; cvt.u32.u64 %0, t; }"
        : "=r"(a) : "l"(p));
    return a;
}

#define CPA(dst, src) \
    asm volatile("cp.async.cg.shared.global [%0], [%1], 16;" :: "r"(dst), "l"(src) : "memory")
#define CPCOMMIT() asm volatile("cp.async.commit_group;" ::: "memory")
#define CPWAIT1()  asm volatile("cp.async.wait_group 1;" ::: "memory")

#define LDSM4(R, A) \
    asm volatile("ldmatrix.sync.aligned.m8n8.x4.shared.b16 {%0,%1,%2,%3}, [%4];" \
                 : "=r"((R)[0]), "=r"((R)[1]), "=r"((R)[2]), "=r"((R)[3]) : "r"(A))

#define MMA_BF16(C, A, B0, B1) \
    asm volatile("mma.sync.aligned.m16n8k16.row.col.f32.bf16.bf16.f32 " \
                 "{%0,%1,%2,%3}, {%4,%5,%6,%7}, {%8,%9}, {%0,%1,%2,%3};" \
                 : "+f"((C)[0]), "+f"((C)[1]), "+f"((C)[2]), "+f"((C)[3]) \
                 : "r"((A)[0]), "r"((A)[1]), "r"((A)[2]), "r"((A)[3]), "r"(B0), "r"(B1))

#define MMA_F16(C, A, B0, B1) \
    asm volatile("mma.sync.aligned.m16n8k16.row.col.f32.f16.f16.f32 " \
                 "{%0,%1,%2,%3}, {%4,%5,%6,%7}, {%8,%9}, {%0,%1,%2,%3};" \
                 : "+f"((C)[0]), "+f"((C)[1]), "+f"((C)[2]), "+f"((C)[3]) \
                 : "r"((A)[0]), "r"((A)[1]), "r"((A)[2]), "r"((A)[3]), "r"(B0), "r"(B1))

__device__ __forceinline__ void split_store(float v, __nv_bfloat16* h, __nv_bfloat16* l,
                                            long long idx) {
    __nv_bfloat16 hi = __float2bfloat16(v);
    h[idx] = hi;
    l[idx] = __float2bfloat16(v - __bfloat162float(hi));
}

// ---------------- conversion kernels ----------------
__global__ void split3_kernel(const float* __restrict__ x,
                              __nv_bfloat16* __restrict__ h,
                              __nv_bfloat16* __restrict__ l,
                              __half* __restrict__ f, long long n) {
    long long i = ((long long)blockIdx.x * blockDim.x + threadIdx.x) * 4;
    if (i >= n) return;
    float4 v = *(const float4*)(x + i);
    __nv_bfloat162 h0, h1, l0, l1;
    h0.x = __float2bfloat16(v.x); l0.x = __float2bfloat16(v.x - __bfloat162float(h0.x));
    h0.y = __float2bfloat16(v.y); l0.y = __float2bfloat16(v.y - __bfloat162float(h0.y));
    h1.x = __float2bfloat16(v.z); l1.x = __float2bfloat16(v.z - __bfloat162float(h1.x));
    h1.y = __float2bfloat16(v.w); l1.y = __float2bfloat16(v.w - __bfloat162float(h1.y));
    *(__nv_bfloat162*)(h + i) = h0; *(__nv_bfloat162*)(h + i + 2) = h1;
    *(__nv_bfloat162*)(l + i) = l0; *(__nv_bfloat162*)(l + i + 2) = l1;
    __half2 f0, f1;
    f0.x = __float2half(v.x); f0.y = __float2half(v.y);
    f1.x = __float2half(v.z); f1.y = __float2half(v.w);
    *(__half2*)(f + i) = f0; *(__half2*)(f + i + 2) = f1;
}

__global__ void tohalf_kernel(const float* __restrict__ x,
                              __half* __restrict__ h, long long n) {
    long long i = ((long long)blockIdx.x * blockDim.x + threadIdx.x) * 4;
    if (i >= n) return;
    float4 v = *(const float4*)(x + i);
    __half2 h0, h1;
    h0.x = __float2half(v.x); h0.y = __float2half(v.y);
    h1.x = __float2half(v.z); h1.y = __float2half(v.w);
    *(__half2*)(h + i) = h0; *(__half2*)(h + i + 2) = h1;
}

__global__ void build_wqk_kernel(const float* __restrict__ Wq, const float* __restrict__ bq,
                                 const float* __restrict__ Wk, const float* __restrict__ bk,
                                 __nv_bfloat16* __restrict__ wh, __nv_bfloat16* __restrict__ wl,
                                 float* __restrict__ bqk) {
    long long i = (long long)blockIdx.x * blockDim.x + threadIdx.x;
    if (i >= (long long)NWQK * LL) return;
    int r = (int)(i / LL), c = (int)(i % LL);
    float v = (r < HH) ? Wq[r * LL + c] : (r < 2 * HH) ? Wk[(r - HH) * LL + c] : 0.f;
    split_store(v, wh, wl, i);
    if (c == 0) bqk[r] = (r < HH) ? bq[r] : (r < 2 * HH) ? bk[r - HH] : 0.f;
}

// ---------------- softmax (fp32 in, fp16 out) ----------------
__global__ __launch_bounds__(256)
void softmax_f16_kernel(const float* __restrict__ E, __half* __restrict__ ah) {
    const long long row = blockIdx.x;
    const float* p = E + row * NN;
    const int tid = threadIdx.x;

    float4 v0 = *(const float4*)(p + tid * 4);
    float4 v1 = *(const float4*)(p + 1024 + tid * 4);

    float m = fmaxf(fmaxf(fmaxf(v0.x, v0.y), fmaxf(v0.z, v0.w)),
                    fmaxf(fmaxf(v1.x, v1.y), fmaxf(v1.z, v1.w)));
    #pragma unroll
    for (int o = 16; o > 0; o >>= 1) m = fmaxf(m, __shfl_xor_sync(0xffffffffu, m, o));

    __shared__ float rmax[8], rsum[8];
    if ((tid & 31) == 0) rmax[tid >> 5] = m;
    __syncthreads();
    float rowmax = rmax[0];
    #pragma unroll
    for (int i = 1; i < 8; i++) rowmax = fmaxf(rowmax, rmax[i]);

    v0.x = __expf(v0.x - rowmax); v0.y = __expf(v0.y - rowmax);
    v0.z = __expf(v0.z - rowmax); v0.w = __expf(v0.w - rowmax);
    v1.x = __expf(v1.x - rowmax); v1.y = __expf(v1.y - rowmax);
    v1.z = __expf(v1.z - rowmax); v1.w = __expf(v1.w - rowmax);

    float s = v0.x + v0.y + v0.z + v0.w + v1.x + v1.y + v1.z + v1.w;
    #pragma unroll
    for (int o = 16; o > 0; o >>= 1) s += __shfl_xor_sync(0xffffffffu, s, o);
    if ((tid & 31) == 0) rsum[tid >> 5] = s;
    __syncthreads();
    float tot = 0.f;
    #pragma unroll
    for (int i = 0; i < 8; i++) tot += rsum[i];

    const float inv = 1.f / tot;
    long long base = row * NN;
    __half2 o0, o1;
    o0.x = __float2half(v0.x * inv); o0.y = __float2half(v0.y * inv);
    o1.x = __float2half(v0.z * inv); o1.y = __float2half(v0.w * inv);
    *(__half2*)(ah + base + tid * 4) = o0;
    *(__half2*)(ah + base + tid * 4 + 2) = o1;
    o0.x = __float2half(v1.x * inv); o0.y = __float2half(v1.y * inv);
    o1.x = __float2half(v1.z * inv); o1.y = __float2half(v1.w * inv);
    *(__half2*)(ah + base + 1024 + tid * 4) = o0;
    *(__half2*)(ah + base + 1024 + tid * 4 + 2) = o1;
}

// ---------------- 3-term bf16 split GEMM body (128x128, BKT=32) -------------
template <int MODE>
__device__ __forceinline__
void gemm_body3(char* smem, int m0, int n0, int bz, int nvalid,
                const uint16_t* __restrict__ Ah, const uint16_t* __restrict__ Al,
                int lda, long long sA,
                const uint16_t* __restrict__ Bh, const uint16_t* __restrict__ Bl,
                int ldb, long long sB,
                float* __restrict__ fout, const float* __restrict__ bias,
                __nv_bfloat16* __restrict__ o0, __nv_bfloat16* __restrict__ o1,
                __nv_bfloat16* __restrict__ o2, __nv_bfloat16* __restrict__ o3,
                int K)
{
    constexpr int TSZ = 128 * 64;
    constexpr int SSZ = 4 * TSZ;
    const uint32_t sb0 = smem_u32(smem);

    const int tid = threadIdx.x, lane = tid & 31, wid = tid >> 5;

    Ah += bz * sA; Bh += bz * sB; Al += bz * sA; Bl += bz * sB;

    auto swz = [](int row, int ch) -> uint32_t {
        return (uint32_t)(row * 64 + ((ch ^ ((row >> 1) & 3)) << 4));
    };

    auto load_stage = [&](int kt, int s) {
        const uint32_t sb = sb0 + (uint32_t)s * SSZ;
        const int k0 = kt * 32;
        #pragma unroll
        for (int i = 0; i < 2; i++) {
            int c = tid + i * 256;
            int row = c >> 2, ch = c & 3;
            uint32_t off = swz(row, ch);
            CPA(sb + off,            Ah + (long long)(m0 + row) * lda + k0 + ch * 8);
            CPA(sb + TSZ + off,      Al + (long long)(m0 + row) * lda + k0 + ch * 8);
            CPA(sb + 2 * TSZ + off,  Bh + (long long)(n0 + row) * ldb + k0 + ch * 8);
            CPA(sb + 3 * TSZ + off,  Bl + (long long)(n0 + row) * ldb + k0 + ch * 8);
        }
        CPCOMMIT();
    };

    const int nk = K / 32;
    load_stage(0, 0);
    load_stage(1, 1);

    const int wm = (wid >> 2) * 64;
    const int wn = (wid & 3) * 32;
    const bool active = (wn < nvalid);

    float acc[4][4][4];
    #pragma unroll
    for (int i = 0; i < 4; i++)
        #pragma unroll
        for (int j = 0; j < 4; j++)
            #pragma unroll
            for (int r = 0; r < 4; r++) acc[i][j][r] = 0.f;

    const int arow = wm + (lane & 7) + (lane & 8);
    const int brow = wn + (lane & 7) + ((lane & 16) >> 1);
    const int acc_k = (lane >> 4);
    const int bcc_k = ((lane >> 3) & 1);

    for (int t = 0; t < nk; t++) {
        const int s = t % 3;
        CPWAIT1();
        __syncthreads();
        if (t + 2 < nk) load_stage(t + 2, (t + 2) % 3);
        else CPCOMMIT();

        if (active) {
            const uint32_t sb = sb0 + (uint32_t)s * SSZ;
            #pragma unroll
            for (int ks = 0; ks < 2; ks++) {
                uint32_t ah[4][4];
                #pragma unroll
                for (int i = 0; i < 4; i++) {
                    int row = arow + i * 16;
                    int cc  = ks * 2 + acc_k;
                    LDSM4(ah[i], sb + swz(row, cc));
                }
                uint32_t bh[4][2];
                #pragma unroll
                for (int j2 = 0; j2 < 2; j2++) {
                    int row = brow + j2 * 16;
                    int cc  = ks * 2 + bcc_k;
                    uint32_t r[4];
                    LDSM4(r, sb + 2 * TSZ + swz(row, cc));
                    bh[2 * j2][0] = r[0]; bh[2 * j2][1] = r[1];
                    bh[2 * j2 + 1][0] = r[2]; bh[2 * j2 + 1][1] = r[3];
                }
                #pragma unroll
                for (int i = 0; i < 4; i++)
                    #pragma unroll
                    for (int j = 0; j < 4; j++)
                        MMA_BF16(acc[i][j], ah[i], bh[j][0], bh[j][1]);

                {
                    uint32_t bl[4][2];
                    #pragma unroll
                    for (int j2 = 0; j2 < 2; j2++) {
                        int row = brow + j2 * 16;
                        int cc  = ks * 2 + bcc_k;
                        uint32_t r[4];
                        LDSM4(r, sb + 3 * TSZ + swz(row, cc));
                        bl[2 * j2][0] = r[0]; bl[2 * j2][1] = r[1];
                        bl[2 * j2 + 1][0] = r[2]; bl[2 * j2 + 1][1] = r[3];
                    }
                    #pragma unroll
                    for (int i = 0; i < 4; i++)
                        #pragma unroll
                        for (int j = 0; j < 4; j++)
                            MMA_BF16(acc[i][j], ah[i], bl[j][0], bl[j][1]);
                }
                #pragma unroll
                for (int i = 0; i < 4; i++) {
                    int row = arow + i * 16;
                    int cc  = ks * 2 + acc_k;
                    LDSM4(ah[i], sb + TSZ + swz(row, cc));
                }
                #pragma unroll
                for (int i = 0; i < 4; i++)
                    #pragma unroll
                    for (int j = 0; j < 4; j++)
                        MMA_BF16(acc[i][j], ah[i], bh[j][0], bh[j][1]);
            }
        }
    }

    if (!active) return;
    const int g = lane >> 2, t4 = lane & 3;
    #pragma unroll
    for (int i = 0; i < 4; i++) {
        #pragma unroll
        for (int j = 0; j < 4; j++) {
            #pragma unroll
            for (int half = 0; half < 2; half++) {
                const int m = m0 + wm + i * 16 + g + half * 8;
                const int n = n0 + wn + j * 8 + t4 * 2;
                float v0 = acc[i][j][half * 2 + 0];
                float v1 = acc[i][j][half * 2 + 1];
                if (MODE == 2) {
                    float2* dst = (float2*)(fout + (long long)bz * NN * NN +
                                            (long long)m * NN + n);
                    *dst = make_float2(v0, v1);
                } else {
                    #pragma unroll
                    for (int e = 0; e < 2; e++) {
                        int nn = n + e;
                        float val = (e ? v1 : v0) + bias[nn];
                        if (nn < HH)
                            split_store(val, o0, o1, (long long)m * KQK + nn);
                        else if (nn < 2 * HH)
                            split_store(val, o2, o3, (long long)m * KQK + (nn - HH));
                    }
                }
            }
        }
    }
}

// ---------------- fp16 single-term GEMM body (128x128, BKT=64) --------------
template <int MODE>
__device__ __forceinline__
void gemm_f16(char* smem, int m0, int n0, int bz,
              const uint16_t* __restrict__ A, int lda, long long sA,
              const uint16_t* __restrict__ B, int ldb, long long sB,
              float* __restrict__ fout, const float* __restrict__ bias,
              const float* __restrict__ resid, __half* __restrict__ ohalf,
              int K)
{
    constexpr int TSZ = 128 * 128;
    constexpr int SSZ = 2 * TSZ;
    const uint32_t sb0 = smem_u32(smem);

    const int tid = threadIdx.x, lane = tid & 31, wid = tid >> 5;

    A += bz * sA; B += bz * sB;

    auto swz = [](int row, int ch) -> uint32_t {
        return (uint32_t)(row * 128 + ((ch ^ (row & 7)) << 4));
    };

    auto load_stage = [&](int kt, int s) {
        const uint32_t sb = sb0 + (uint32_t)s * SSZ;
        const int k0 = kt * 64;
        #pragma unroll
        for (int i = 0; i < 4; i++) {
            int c = tid + i * 256;
            int row = c >> 3, ch = c & 7;
            uint32_t off = swz(row, ch);
            CPA(sb + off,       A + (long long)(m0 + row) * lda + k0 + ch * 8);
            CPA(sb + TSZ + off, B + (long long)(n0 + row) * ldb + k0 + ch * 8);
        }
        CPCOMMIT();
    };

    const int nk = K / 64;
    load_stage(0, 0);
    load_stage(1, 1);

    const int wm = (wid >> 2) * 64;
    const int wn = (wid & 3) * 32;

    float acc[4][4][4];
    #pragma unroll
    for (int i = 0; i < 4; i++)
        #pragma unroll
        for (int j = 0; j < 4; j++)
            #pragma unroll
            for (int r = 0; r < 4; r++) acc[i][j][r] = 0.f;

    const int arow = wm + (lane & 7) + (lane & 8);
    const int brow = wn + (lane & 7) + ((lane & 16) >> 1);
    const int acc_k = (lane >> 4);
    const int bcc_k = ((lane >> 3) & 1);

    for (int t = 0; t < nk; t++) {
        const int s = t % 3;
        CPWAIT1();
        __syncthreads();
        if (t + 2 < nk) load_stage(t + 2, (t + 2) % 3);
        else CPCOMMIT();

        const uint32_t sb = sb0 + (uint32_t)s * SSZ;
        #pragma unroll
        for (int ks = 0; ks < 4; ks++) {
            uint32_t ah[4][4];
            #pragma unroll
            for (int i = 0; i < 4; i++) {
                int row = arow + i * 16;
                int cc  = ks * 2 + acc_k;
                LDSM4(ah[i], sb + swz(row, cc));
            }
            uint32_t bh[4][2];
            #pragma unroll
            for (int j2 = 0; j2 < 2; j2++) {
                int row = brow + j2 * 16;
                int cc  = ks * 2 + bcc_k;
                uint32_t r[4];
                LDSM4(r, sb + TSZ + swz(row, cc));
                bh[2 * j2][0] = r[0]; bh[2 * j2][1] = r[1];
                bh[2 * j2 + 1][0] = r[2]; bh[2 * j2 + 1][1] = r[3];
            }
            #pragma unroll
            for (int i = 0; i < 4; i++)
                #pragma unroll
                for (int j = 0; j < 4; j++)
                    MMA_F16(acc[i][j], ah[i], bh[j][0], bh[j][1]);
        }
    }

    const int g = lane >> 2, t4 = lane & 3;
    #pragma unroll
    for (int i = 0; i < 4; i++) {
        #pragma unroll
        for (int j = 0; j < 4; j++) {
            #pragma unroll
            for (int half = 0; half < 2; half++) {
                const int m = m0 + wm + i * 16 + g + half * 8;
                const int n = n0 + wn + j * 8 + t4 * 2;
                float v0 = acc[i][j][half * 2 + 0];
                float v1 = acc[i][j][half * 2 + 1];
                if (MODE == 3) {
                    const long long off = (long long)bz * NN * LL + (long long)m * LL + n;
                    float2 rx = *(const float2*)(resid + off);
                    *(float2*)(fout + off) = make_float2(v0 + rx.x, v1 + rx.y);
                } else {
                    const int b = m >> 11, ii = m & (NN - 1);
                    long long i0 = (((long long)(b * LL + n)) << 11) + ii;
                    long long i1 = (((long long)(b * LL + n + 1)) << 11) + ii;
                    ohalf[i0] = __float2half(v0 + bias[n]);
                    ohalf[i1] = __float2half(v1 + bias[n + 1]);
                }
            }
        }
    }
}

// ---------------- kernel wrappers ----------------
__global__ __launch_bounds__(256, 2)
void proj_qk_kernel(const __nv_bfloat16* __restrict__ xh, const __nv_bfloat16* __restrict__ xl,
                    const __nv_bfloat16* __restrict__ wqkh, const __nv_bfloat16* __restrict__ wqkl,
                    const float* __restrict__ bqk,
                    __nv_bfloat16* __restrict__ qh, __nv_bfloat16* __restrict__ ql,
                    __nv_bfloat16* __restrict__ kh, __nv_bfloat16* __restrict__ kl)
{
    extern __shared__ char smem[];
    const int bx = blockIdx.x;
    const int nvalid = (bx == 2) ? 64 : 128;
    gemm_body3<0>(smem, blockIdx.y * 128, bx * 128, 0, nvalid,
                  (const uint16_t*)xh, (const uint16_t*)xl, LL, 0,
                  (const uint16_t*)wqkh, (const uint16_t*)wqkl, LL, 0,
                  nullptr, bqk, qh, ql, kh, kl, LL);
}

__global__ __launch_bounds__(256, 2)
void proj_v_kernel(const __half* __restrict__ xf, const __half* __restrict__ wvh,
                   const float* __restrict__ bv, __half* __restrict__ vth)
{
    extern __shared__ char smem[];
    gemm_f16<1>(smem, blockIdx.y * 128, blockIdx.x * 128, 0,
                (const uint16_t*)xf, LL, 0, (const uint16_t*)wvh, LL, 0,
                nullptr, bv, nullptr, vth, LL);
}

__global__ __launch_bounds__(256, 2)
void energy_kernel(const __nv_bfloat16* __restrict__ qh, const __nv_bfloat16* __restrict__ ql,
                   const __nv_bfloat16* __restrict__ kh, const __nv_bfloat16* __restrict__ kl,
                   float* __restrict__ e)
{
    extern __shared__ char smem[];
    gemm_body3<2>(smem, blockIdx.y * 128, blockIdx.x * 128, blockIdx.z, 128,
                  (const uint16_t*)qh, (const uint16_t*)ql, KQK, (long long)NN * KQK,
                  (const uint16_t*)kh, (const uint16_t*)kl, KQK, (long long)NN * KQK,
                  e, nullptr, nullptr, nullptr, nullptr, nullptr, KQK);
}

__global__ __launch_bounds__(256, 2)
void attnv_kernel(const __half* __restrict__ ath, const __half* __restrict__ vth,
                  const float* __restrict__ x, float* __restrict__ out)
{
    extern __shared__ char smem[];
    gemm_f16<3>(smem, blockIdx.y * 128, blockIdx.x * 128, blockIdx.z,
                (const uint16_t*)ath, NN, (long long)NN * NN,
                (const uint16_t*)vth, NN, (long long)LL * NN,
                out, nullptr, x, nullptr, NN);
}

// ---------------- host side ----------------
extern "C" void kernel_launch(void* const* d_in, const int* in_sizes, int n_in,
                              void* d_out, int out_size) {
    const float* x  = (const float*)d_in[0];
    const float* Wq = (const float*)d_in[1];
    const float* bq = (const float*)d_in[2];
    const float* Wk = (const float*)d_in[3];
    const float* bk = (const float*)d_in[4];
    const float* Wv = (const float*)d_in[5];
    const float* bv = (const float*)d_in[6];
    float* out = (float*)d_out;

    __nv_bfloat16 *xh, *xl, *wqkh, *wqkl, *qh, *ql, *kh, *kl;
    __half *xf, *wvh, *ath, *vth;
    float *e, *bqk;
    cudaGetSymbolAddress((void**)&xh, g_xh);     cudaGetSymbolAddress((void**)&xl, g_xl);
    cudaGetSymbolAddress((void**)&xf, g_xf);
    cudaGetSymbolAddress((void**)&wqkh, g_wqkh); cudaGetSymbolAddress((void**)&wqkl, g_wqkl);
    cudaGetSymbolAddress((void**)&wvh, g_wvh);
    cudaGetSymbolAddress((void**)&qh, g_qh);     cudaGetSymbolAddress((void**)&ql, g_ql);
    cudaGetSymbolAddress((void**)&kh, g_kh);     cudaGetSymbolAddress((void**)&kl, g_kl);
    cudaGetSymbolAddress((void**)&e, g_e);
    cudaGetSymbolAddress((void**)&ath, g_ath);
    cudaGetSymbolAddress((void**)&vth, g_vth);
    cudaGetSymbolAddress((void**)&bqk, g_bqk);

    constexpr int SMEM = 3 * 32768;
    static cudaStream_t s1 = nullptr;
    static cudaEvent_t evPre = nullptr, evV = nullptr;
    if (!s1) {
        cudaFuncSetAttribute((const void*)proj_qk_kernel,
                             cudaFuncAttributeMaxDynamicSharedMemorySize, SMEM);
        cudaFuncSetAttribute((const void*)proj_v_kernel,
                             cudaFuncAttributeMaxDynamicSharedMemorySize, SMEM);
        cudaFuncSetAttribute((const void*)energy_kernel,
                             cudaFuncAttributeMaxDynamicSharedMemorySize, SMEM);
        cudaFuncSetAttribute((const void*)attnv_kernel,
                             cudaFuncAttributeMaxDynamicSharedMemorySize, SMEM);
        cudaStreamCreateWithFlags(&s1, cudaStreamNonBlocking);
        cudaEventCreateWithFlags(&evPre, cudaEventDisableTiming);
        cudaEventCreateWithFlags(&evV, cudaEventDisableTiming);
    }

    // conversions (stream 0) — fused single-pass over x
    {
        long long n = (long long)MTOT * LL;
        split3_kernel<<<(unsigned)(n / 4 / 256), 256>>>(x, xh, xl, xf, n);
    }
    build_wqk_kernel<<<(NWQK * LL + 255) / 256, 256>>>(Wq, bq, Wk, bk, wqkh, wqkl, bqk);
    {
        long long n = (long long)LL * LL;
        tohalf_kernel<<<(unsigned)((n / 4 + 255) / 256), 256>>>(Wv, wvh, n);
    }

    // fork: v-proj on s1, overlapping qkproj tail + energy + softmax
    cudaEventRecord(evPre, 0);
    cudaStreamWaitEvent(s1, evPre, 0);
    proj_v_kernel<<<dim3(LL / 128, MTOT / 128, 1), 256, SMEM, s1>>>(xf, wvh, bv, vth);
    cudaEventRecord(evV, s1);

    // stream 0: qk projection -> energy -> softmax
    proj_qk_kernel<<<dim3(3, MTOT / 128, 1), 256, SMEM>>>(
        xh, xl, wqkh, wqkl, bqk, qh, ql, kh, kl);
    energy_kernel<<<dim3(NN / 128, NN / 128, BB), 256, SMEM>>>(qh, ql, kh, kl, e);
    softmax_f16_kernel<<<MTOT, 256>>>(e, ath);

    // join v-proj, then attn@v + residual
    cudaStreamWaitEvent(0, evV, 0);
    attnv_kernel<<<dim3(LL / 128, NN / 128, BB), 256, SMEM>>>(ath, vth, x, out);
}